// round 1
// baseline (speedup 1.0000x reference)
#include <cuda_runtime.h>
#include <cstdint>
#include <math.h>

#define Bdim 16
#define Tdim 2048
#define Ddim 512
#define Hdim 512

// ---------------- f32x2 helpers (packed fp32 pairs, 2x FFMA throughput) ----
__device__ __forceinline__ unsigned long long pk2(float x, float y) {
    unsigned long long r;
    asm("mov.b64 %0, {%1,%2};" : "=l"(r) : "f"(x), "f"(y));
    return r;
}
__device__ __forceinline__ void fma2(unsigned long long& d, unsigned long long a, unsigned long long b) {
    asm("fma.rn.f32x2 %0, %1, %2, %0;" : "+l"(d) : "l"(a), "l"(b));
}
__device__ __forceinline__ void add2(unsigned long long& d, unsigned long long a) {
    asm("add.rn.f32x2 %0, %0, %1;" : "+l"(d) : "l"(a));
}
__device__ __forceinline__ float2 upk2(unsigned long long v) {
    float2 f;
    asm("mov.b64 {%0,%1}, %2;" : "=f"(f.x), "=f"(f.y) : "l"(v));
    return f;
}
__device__ __forceinline__ uint32_t s2u(const void* p) {
    uint32_t a;
    asm("{ .reg .u64 t; cvta.to.shared.u64 t, %1; cvt.u32.u64 %0, t; }" : "=r"(a) : "l"(p));
    return a;
}

// ---------------- Phase 1: pre = x @ W_xh + b  (fp32 SGEMM, f32x2) --------
// M = B*T = 32768, K = 512, N = 512. Writes straight into d_out (in-place
// pre buffer; the RNN kernel overwrites each element after consuming it).
#define GTM 128
#define GTN 128
#define GTK 16

__global__ void __launch_bounds__(256, 2)
gemm_pre_kernel(const float* __restrict__ X, const float* __restrict__ W,
                const float* __restrict__ bias, float* __restrict__ out) {
    __shared__ __align__(16) float As[2][GTK][GTM];  // A stored [k][m] (transposed)
    __shared__ __align__(16) float Bs[2][GTK][GTN];

    const int tid = threadIdx.x;
    const int mb = blockIdx.x * GTM;
    const int nb = blockIdx.y * GTN;
    const int K = Ddim, N = Hdim;

    unsigned long long acc[8][4];
#pragma unroll
    for (int i = 0; i < 8; i++)
#pragma unroll
        for (int q = 0; q < 4; q++) acc[i][q] = 0ull;

    const int tm = (tid >> 4) << 3;  // 8 rows per thread
    const int tn = (tid & 15) << 3;  // 8 cols per thread

    auto loadA = [&](int kt, int buf) {
#pragma unroll
        for (int i = 0; i < 2; i++) {
            int idx = tid + i * 256;          // 0..511 float4 loads
            int row = idx >> 2;               // 0..127
            int kq  = (idx & 3) << 2;         // 0,4,8,12
            float4 v = *(const float4*)(X + (size_t)(mb + row) * K + kt * GTK + kq);
            As[buf][kq + 0][row] = v.x;
            As[buf][kq + 1][row] = v.y;
            As[buf][kq + 2][row] = v.z;
            As[buf][kq + 3][row] = v.w;
        }
    };
    auto loadB = [&](int kt, int buf) {
#pragma unroll
        for (int i = 0; i < 2; i++) {
            int idx = tid + i * 256;
            int kk = idx >> 5;                // 0..15
            int nq = (idx & 31) << 2;         // 0..124
            *(float4*)(&Bs[buf][kk][nq]) =
                *(const float4*)(W + (size_t)(kt * GTK + kk) * N + nb + nq);
        }
    };

    loadA(0, 0);
    loadB(0, 0);
    __syncthreads();

    const int NT = K / GTK;  // 32
    for (int kt = 0; kt < NT; ++kt) {
        const int cur = kt & 1;
        if (kt + 1 < NT) {
            loadA(kt + 1, cur ^ 1);
            loadB(kt + 1, cur ^ 1);
        }
#pragma unroll
        for (int kk = 0; kk < GTK; ++kk) {
            float4 A0 = *(const float4*)(&As[cur][kk][tm]);
            float4 A1 = *(const float4*)(&As[cur][kk][tm + 4]);
            ulonglong2 B0 = *(const ulonglong2*)(&Bs[cur][kk][tn]);
            ulonglong2 B1 = *(const ulonglong2*)(&Bs[cur][kk][tn + 4]);
            float av[8] = {A0.x, A0.y, A0.z, A0.w, A1.x, A1.y, A1.z, A1.w};
#pragma unroll
            for (int mi = 0; mi < 8; ++mi) {
                unsigned long long ai = pk2(av[mi], av[mi]);
                fma2(acc[mi][0], ai, B0.x);
                fma2(acc[mi][1], ai, B0.y);
                fma2(acc[mi][2], ai, B1.x);
                fma2(acc[mi][3], ai, B1.y);
            }
        }
        __syncthreads();
    }

    unsigned long long bz[4];
#pragma unroll
    for (int q = 0; q < 4; q++)
        bz[q] = pk2(bias[nb + tn + 2 * q], bias[nb + tn + 2 * q + 1]);
#pragma unroll
    for (int mi = 0; mi < 8; ++mi) {
#pragma unroll
        for (int q = 0; q < 4; q++) {
            add2(acc[mi][q], bz[q]);
            *(unsigned long long*)(out + (size_t)(mb + tm + mi) * N + nb + tn + 2 * q) =
                acc[mi][q];
        }
    }
}

// ---------------- Phase 2: sequential tanh RNN -----------------------------
// 16 clusters (one per batch element) x 8 CTAs x 512 threads.
// Each CTA owns 64 output columns; W_hh[:, jslice] lives in registers
// (32 f32x2 pairs/thread = 64 k-terms per thread, 8 threads per column).
// h state (512 floats) replicated in every CTA's SMEM, double-buffered;
// new values broadcast to all 8 CTAs via DSMEM stores + cluster.sync.
__global__ void __launch_bounds__(512, 1) __cluster_dims__(8, 1, 1)
rnn_kernel(const float* __restrict__ W_hh, float* __restrict__ out) {
    __shared__ __align__(16) float hbuf[2][Hdim];

    const int tid  = threadIdx.x;
    const int lane = tid & 31;
    const int warp = tid >> 5;
    unsigned rank;
    asm("mov.u32 %0, %%cluster_ctarank;" : "=r"(rank));
    const int batch = blockIdx.x >> 3;

    const int cg   = lane >> 3;        // column-subgroup within warp (0..3)
    const int sub  = lane & 7;         // position within 8-thread reduce group
    const int cloc = warp * 4 + cg;    // local column 0..63
    const int j    = (int)rank * 64 + cloc;  // global column 0..511
    const int k0   = sub * 64;         // this thread's k-chunk

    // Load W_hh[k0..k0+63, j] into registers as 32 packed f32x2 pairs.
    unsigned long long w[32];
#pragma unroll
    for (int i = 0; i < 32; i++) {
        float a = W_hh[(size_t)(k0 + 2 * i) * Hdim + j];
        float b = W_hh[(size_t)(k0 + 2 * i + 1) * Hdim + j];
        w[i] = pk2(a, b);
    }

    // h0 = 0
    for (int i = tid; i < 2 * Hdim; i += 512) (&hbuf[0][0])[i] = 0.f;

    const bool writer = (sub == 0);  // lanes 0,8,16,24 of each warp

    // Precompute DSMEM base address of hbuf in every cluster CTA.
    uint32_t rbase[8];
    const uint32_t lbase = s2u(&hbuf[0][0]);
#pragma unroll
    for (int r = 0; r < 8; r++) {
        asm("mapa.shared::cluster.u32 %0, %1, %2;" : "=r"(rbase[r]) : "r"(lbase), "r"(r));
    }

    float* outp = out + (size_t)batch * Tdim * Hdim + j;  // pre in / h out
    float pre_cur = writer ? outp[0] : 0.f;

    // All hbufs zeroed before any remote write can land.
    asm volatile("barrier.cluster.arrive.aligned;\n\tbarrier.cluster.wait.aligned;" ::: "memory");

    for (int t = 0; t < Tdim; ++t) {
        const int p = t & 1;

        // Prefetch next step's pre early (hides DRAM latency behind compute+sync).
        float pre_next = 0.f;
        if (writer && (t + 1 < Tdim)) pre_next = outp[(size_t)(t + 1) * Hdim];

        // Partial dot: 64 k-terms as 16 LDS.128 + 32 fma.f32x2.
        const ulonglong2* hv = (const ulonglong2*)(&hbuf[p][k0]);
        unsigned long long acc0 = 0ull, acc1 = 0ull;
#pragma unroll
        for (int i = 0; i < 16; i++) {
            ulonglong2 hp = hv[i];
            fma2(acc0, hp.x, w[2 * i]);
            fma2(acc1, hp.y, w[2 * i + 1]);
        }
        float2 a0 = upk2(acc0), a1 = upk2(acc1);
        float acc = (a0.x + a0.y) + (a1.x + a1.y);
        acc += __shfl_xor_sync(0xffffffffu, acc, 4);
        acc += __shfl_xor_sync(0xffffffffu, acc, 2);
        acc += __shfl_xor_sync(0xffffffffu, acc, 1);

        if (writer) {
            float hn = tanhf(pre_cur + acc);
            outp[(size_t)t * Hdim] = hn;  // final output for (batch, t, j)
            // Broadcast to every CTA's next-step buffer (incl. self) via DSMEM.
            const uint32_t off = (uint32_t)(((p ^ 1) * Hdim + j) * 4);
#pragma unroll
            for (int r = 0; r < 8; r++) {
                asm volatile("st.shared::cluster.f32 [%0], %1;"
                             :: "r"(rbase[r] + off), "f"(hn) : "memory");
            }
            pre_cur = pre_next;
        }

        // Release own stores / acquire everyone's before next step reads buf[p^1].
        asm volatile("barrier.cluster.arrive.aligned;\n\tbarrier.cluster.wait.aligned;" ::: "memory");
    }
}

// ---------------- launch ---------------------------------------------------
extern "C" void kernel_launch(void* const* d_in, const int* in_sizes, int n_in,
                              void* d_out, int out_size) {
    const float* x    = (const float*)d_in[0];  // [16, 2048, 512]
    const float* W_xh = (const float*)d_in[1];  // [512, 512]
    const float* W_hh = (const float*)d_in[2];  // [512, 512]
    const float* b    = (const float*)d_in[3];  // [512]
    // d_in[4] = A (DFA feedback matrix) — backward-only, unused in forward.
    float* out = (float*)d_out;                 // [16, 2048, 512]

    dim3 ggrid((Bdim * Tdim) / GTM, Hdim / GTN);  // (256, 4)
    gemm_pre_kernel<<<ggrid, 256>>>(x, W_xh, b, out);

    // 16 batches x 8-CTA clusters = 128 CTAs.
    rnn_kernel<<<128, 512>>>(W_hh, out);
}

// round 2
// speedup vs baseline: 1.0364x; 1.0364x over previous
#include <cuda_runtime.h>
#include <cstdint>
#include <math.h>

#define Bdim 16
#define Tdim 2048
#define Ddim 512
#define Hdim 512

// ---------------- f32x2 helpers (packed fp32 pairs, 2x FFMA throughput) ----
__device__ __forceinline__ unsigned long long pk2(float x, float y) {
    unsigned long long r;
    asm("mov.b64 %0, {%1,%2};" : "=l"(r) : "f"(x), "f"(y));
    return r;
}
__device__ __forceinline__ void fma2(unsigned long long& d, unsigned long long a, unsigned long long b) {
    asm("fma.rn.f32x2 %0, %1, %2, %0;" : "+l"(d) : "l"(a), "l"(b));
}
__device__ __forceinline__ void add2(unsigned long long& d, unsigned long long a) {
    asm("add.rn.f32x2 %0, %0, %1;" : "+l"(d) : "l"(a));
}
__device__ __forceinline__ float2 upk2(unsigned long long v) {
    float2 f;
    asm("mov.b64 {%0,%1}, %2;" : "=f"(f.x), "=f"(f.y) : "l"(v));
    return f;
}
__device__ __forceinline__ uint32_t s2u(const void* p) {
    uint32_t a;
    asm("{ .reg .u64 t; cvta.to.shared.u64 t, %1; cvt.u32.u64 %0, t; }" : "=r"(a) : "l"(p));
    return a;
}
__device__ __forceinline__ void mbar_wait(uint32_t bar, uint32_t parity) {
    asm volatile(
        "{\n\t"
        ".reg .pred P;\n\t"
        "LAB_W%=:\n\t"
        "mbarrier.try_wait.parity.acquire.cluster.shared::cta.b64 P, [%0], %1, 0x989680;\n\t"
        "@P bra LAB_D%=;\n\t"
        "bra LAB_W%=;\n\t"
        "LAB_D%=:\n\t"
        "}"
        :: "r"(bar), "r"(parity) : "memory");
}

// ---------------- Phase 1: pre = x @ W_xh + b  (fp32 SGEMM, f32x2) --------
// M = B*T = 32768, K = 512, N = 512. Writes straight into d_out (in-place
// pre buffer; the RNN kernel overwrites each element after consuming it).
#define GTM 128
#define GTN 128
#define GTK 16

__global__ void __launch_bounds__(256, 2)
gemm_pre_kernel(const float* __restrict__ X, const float* __restrict__ W,
                const float* __restrict__ bias, float* __restrict__ out) {
    __shared__ __align__(16) float As[2][GTK][GTM];  // A stored [k][m] (transposed)
    __shared__ __align__(16) float Bs[2][GTK][GTN];

    const int tid = threadIdx.x;
    const int mb = blockIdx.x * GTM;
    const int nb = blockIdx.y * GTN;
    const int K = Ddim, N = Hdim;

    unsigned long long acc[8][4];
#pragma unroll
    for (int i = 0; i < 8; i++)
#pragma unroll
        for (int q = 0; q < 4; q++) acc[i][q] = 0ull;

    const int tm = (tid >> 4) << 3;  // 8 rows per thread
    const int tn = (tid & 15) << 3;  // 8 cols per thread

    auto loadA = [&](int kt, int buf) {
#pragma unroll
        for (int i = 0; i < 2; i++) {
            int idx = tid + i * 256;          // 0..511 float4 loads
            int row = idx >> 2;               // 0..127
            int kq  = (idx & 3) << 2;         // 0,4,8,12
            float4 v = *(const float4*)(X + (size_t)(mb + row) * K + kt * GTK + kq);
            As[buf][kq + 0][row] = v.x;
            As[buf][kq + 1][row] = v.y;
            As[buf][kq + 2][row] = v.z;
            As[buf][kq + 3][row] = v.w;
        }
    };
    auto loadB = [&](int kt, int buf) {
#pragma unroll
        for (int i = 0; i < 2; i++) {
            int idx = tid + i * 256;
            int kk = idx >> 5;                // 0..15
            int nq = (idx & 31) << 2;         // 0..124
            *(float4*)(&Bs[buf][kk][nq]) =
                *(const float4*)(W + (size_t)(kt * GTK + kk) * N + nb + nq);
        }
    };

    loadA(0, 0);
    loadB(0, 0);
    __syncthreads();

    const int NT = K / GTK;  // 32
    for (int kt = 0; kt < NT; ++kt) {
        const int cur = kt & 1;
        if (kt + 1 < NT) {
            loadA(kt + 1, cur ^ 1);
            loadB(kt + 1, cur ^ 1);
        }
#pragma unroll
        for (int kk = 0; kk < GTK; ++kk) {
            float4 A0 = *(const float4*)(&As[cur][kk][tm]);
            float4 A1 = *(const float4*)(&As[cur][kk][tm + 4]);
            ulonglong2 B0 = *(const ulonglong2*)(&Bs[cur][kk][tn]);
            ulonglong2 B1 = *(const ulonglong2*)(&Bs[cur][kk][tn + 4]);
            float av[8] = {A0.x, A0.y, A0.z, A0.w, A1.x, A1.y, A1.z, A1.w};
#pragma unroll
            for (int mi = 0; mi < 8; ++mi) {
                unsigned long long ai = pk2(av[mi], av[mi]);
                fma2(acc[mi][0], ai, B0.x);
                fma2(acc[mi][1], ai, B0.y);
                fma2(acc[mi][2], ai, B1.x);
                fma2(acc[mi][3], ai, B1.y);
            }
        }
        __syncthreads();
    }

    unsigned long long bz[4];
#pragma unroll
    for (int q = 0; q < 4; q++)
        bz[q] = pk2(bias[nb + tn + 2 * q], bias[nb + tn + 2 * q + 1]);
#pragma unroll
    for (int mi = 0; mi < 8; ++mi) {
#pragma unroll
        for (int q = 0; q < 4; q++) {
            add2(acc[mi][q], bz[q]);
            *(unsigned long long*)(out + (size_t)(mb + tm + mi) * N + nb + tn + 2 * q) =
                acc[mi][q];
        }
    }
}

// ---------------- Phase 2: sequential tanh RNN -----------------------------
// 16 clusters (one per batch element) x 8 CTAs x 512 threads.
// Each CTA owns 64 output columns; W_hh[:, jslice] lives in registers.
// Per-step sync: writers STS into own hbuf[p^1] block, __syncthreads, then one
// elected thread DSMEM-bulk-copies the 256B block to the 7 peers, completing
// on each peer's transaction mbarrier (expect_tx = 7*256 = 1792B + 1 arrive).
// No barrier.cluster / no CCTL.IVALL in the loop.
__global__ void __launch_bounds__(512, 1) __cluster_dims__(8, 1, 1)
rnn_kernel(const float* __restrict__ W_hh, float* __restrict__ out) {
    __shared__ __align__(16) float hbuf[2][Hdim];
    __shared__ __align__(8) unsigned long long mbar[2];

    const int tid  = threadIdx.x;
    const int lane = tid & 31;
    const int warp = tid >> 5;
    unsigned rank;
    asm("mov.u32 %0, %%cluster_ctarank;" : "=r"(rank));
    const int batch = blockIdx.x >> 3;

    const int cg   = lane >> 3;        // column-subgroup within warp (0..3)
    const int sub  = lane & 7;         // position within 8-thread reduce group
    const int cloc = warp * 4 + cg;    // local column 0..63
    const int j    = (int)rank * 64 + cloc;  // global column 0..511
    const int k0   = sub * 64;         // this thread's k-chunk

    // Load W_hh[k0..k0+63, j] into registers as 32 packed f32x2 pairs.
    unsigned long long w[32];
#pragma unroll
    for (int i = 0; i < 32; i++) {
        float a = W_hh[(size_t)(k0 + 2 * i) * Hdim + j];
        float b = W_hh[(size_t)(k0 + 2 * i + 1) * Hdim + j];
        w[i] = pk2(a, b);
    }

    // h0 = 0 in both buffers; init the two phase barriers (1 arrival each:
    // the elected thread's arrive.expect_tx).
    for (int i = tid; i < 2 * Hdim; i += 512) (&hbuf[0][0])[i] = 0.f;
    const uint32_t lbase  = s2u(&hbuf[0][0]);
    const uint32_t barOff = s2u(&mbar[0]) - lbase;
    if (tid == 0) {
        asm volatile("mbarrier.init.shared.b64 [%0], 1;" :: "r"(lbase + barOff) : "memory");
        asm volatile("mbarrier.init.shared.b64 [%0], 1;" :: "r"(lbase + barOff + 8) : "memory");
    }
    __syncthreads();
    // One-time cluster rendezvous: barriers+zeroed buffers visible before any
    // peer bulk-copy can land.
    asm volatile("barrier.cluster.arrive.aligned;\n\tbarrier.cluster.wait.aligned;" ::: "memory");

    // DSMEM base address of hbuf in every cluster CTA (offsets are preserved).
    uint32_t rbase[8];
#pragma unroll
    for (int r = 0; r < 8; r++) {
        asm("mapa.shared::cluster.u32 %0, %1, %2;" : "=r"(rbase[r]) : "r"(lbase), "r"(r));
    }

    const bool writer = (sub == 0);  // lanes 0,8,16,24 of each warp
    float* outp = out + (size_t)batch * Tdim * Hdim + j;  // pre in / h out
    float pre_cur = writer ? outp[0] : 0.f;

    uint32_t ph0 = 0, ph1 = 0;

    for (int t = 0; t < Tdim; ++t) {
        const int p = t & 1;

        // Wait for step t's inputs (skip t=0: buffers pre-zeroed).
        if (t > 0) {
            if (p) { mbar_wait(lbase + barOff + 8, ph1); ph1 ^= 1; }
            else   { mbar_wait(lbase + barOff,     ph0); ph0 ^= 1; }
        }

        // Prefetch next step's pre early (hides latency behind compute+sync).
        float pre_next = 0.f;
        if (writer && (t + 1 < Tdim)) pre_next = outp[(size_t)(t + 1) * Hdim];

        // Partial dot: 64 k-terms as 16 LDS.128 + 32 fma.f32x2.
        const ulonglong2* hv = (const ulonglong2*)(&hbuf[p][k0]);
        unsigned long long acc0 = 0ull, acc1 = 0ull;
#pragma unroll
        for (int i = 0; i < 16; i++) {
            ulonglong2 hp = hv[i];
            fma2(acc0, hp.x, w[2 * i]);
            fma2(acc1, hp.y, w[2 * i + 1]);
        }
        float2 a0 = upk2(acc0), a1 = upk2(acc1);
        float acc = (a0.x + a0.y) + (a1.x + a1.y);
        acc += __shfl_xor_sync(0xffffffffu, acc, 4);
        acc += __shfl_xor_sync(0xffffffffu, acc, 2);
        acc += __shfl_xor_sync(0xffffffffu, acc, 1);

        if (writer) {
            float hn = tanhf(pre_cur + acc);
            outp[(size_t)t * Hdim] = hn;       // final output for (batch, t, j)
            hbuf[p ^ 1][j] = hn;               // own block of next-step state
            pre_cur = pre_next;
        }

        if (t + 1 < Tdim) {
            __syncthreads();  // all 64 writer STS of this CTA visible
            if (tid == 0) {
                // Generic-proxy STS -> async-proxy bulk copy ordering.
                asm volatile("fence.proxy.async;" ::: "memory");
                const uint32_t blkOff = (uint32_t)((((p ^ 1) * Hdim) + (int)rank * 64) * 4);
                const uint32_t mbOff  = barOff + 8u * (uint32_t)(p ^ 1);
                // Own barrier: 1 arrive + 7*256 bytes expected this phase.
                asm volatile("mbarrier.arrive.expect_tx.shared::cta.b64 _, [%0], %1;"
                             :: "r"(lbase + mbOff), "r"(1792u) : "memory");
#pragma unroll
                for (int r = 0; r < 8; r++) {
                    if (r != (int)rank) {
                        asm volatile(
                            "cp.async.bulk.shared::cluster.shared::cta.mbarrier::complete_tx::bytes "
                            "[%0], [%1], %2, [%3];"
                            :: "r"(rbase[r] + blkOff), "r"(lbase + blkOff),
                               "r"(256u), "r"(rbase[r] + mbOff)
                            : "memory");
                    }
                }
            }
        }
    }

    // One-time trailing rendezvous before any CTA's SMEM can be retired.
    asm volatile("barrier.cluster.arrive.aligned;\n\tbarrier.cluster.wait.aligned;" ::: "memory");
}

// ---------------- launch ---------------------------------------------------
extern "C" void kernel_launch(void* const* d_in, const int* in_sizes, int n_in,
                              void* d_out, int out_size) {
    const float* x    = (const float*)d_in[0];  // [16, 2048, 512]
    const float* W_xh = (const float*)d_in[1];  // [512, 512]
    const float* W_hh = (const float*)d_in[2];  // [512, 512]
    const float* b    = (const float*)d_in[3];  // [512]
    // d_in[4] = A (DFA feedback matrix) — backward-only, unused in forward.
    float* out = (float*)d_out;                 // [16, 2048, 512]

    dim3 ggrid((Bdim * Tdim) / GTM, Hdim / GTN);  // (256, 4)
    gemm_pre_kernel<<<ggrid, 256>>>(x, W_xh, b, out);

    // 16 batches x 8-CTA clusters = 128 CTAs.
    rnn_kernel<<<128, 512>>>(W_hh, out);
}

// round 3
// speedup vs baseline: 1.5770x; 1.5216x over previous
#include <cuda_runtime.h>
#include <cstdint>
#include <math.h>

#define Bdim 16
#define Tdim 2048
#define Ddim 512
#define Hdim 512

// ---------------- global staging state (no allocations allowed) ------------
__device__ float    g_h[2][Bdim][Hdim];          // double-buffered hidden state
__device__ unsigned g_flag[2][Bdim][8][8];       // [phase][batch][rank][pad 32B]

// ---------------- f32x2 helpers (packed fp32 pairs, 2x FFMA throughput) ----
__device__ __forceinline__ unsigned long long pk2(float x, float y) {
    unsigned long long r;
    asm("mov.b64 %0, {%1,%2};" : "=l"(r) : "f"(x), "f"(y));
    return r;
}
__device__ __forceinline__ void fma2(unsigned long long& d, unsigned long long a, unsigned long long b) {
    asm("fma.rn.f32x2 %0, %1, %2, %0;" : "+l"(d) : "l"(a), "l"(b));
}
__device__ __forceinline__ void add2(unsigned long long& d, unsigned long long a) {
    asm("add.rn.f32x2 %0, %0, %1;" : "+l"(d) : "l"(a));
}
__device__ __forceinline__ float2 upk2(unsigned long long v) {
    float2 f;
    asm("mov.b64 {%0,%1}, %2;" : "=f"(f.x), "=f"(f.y) : "l"(v));
    return f;
}
__device__ __forceinline__ unsigned ldacq(const unsigned* p) {
    unsigned v;
    asm volatile("ld.acquire.gpu.global.u32 %0, [%1];" : "=r"(v) : "l"(p) : "memory");
    return v;
}
__device__ __forceinline__ void strel(unsigned* p, unsigned v) {
    asm volatile("st.release.gpu.global.u32 [%0], %1;" :: "l"(p), "r"(v) : "memory");
}
__device__ __forceinline__ ulonglong2 ldcg128(const void* p) {
    ulonglong2 v;
    asm volatile("ld.global.cg.v2.u64 {%0,%1}, [%2];" : "=l"(v.x), "=l"(v.y) : "l"(p));
    return v;
}
__device__ __forceinline__ void stcg32(float* p, float v) {
    asm volatile("st.global.cg.f32 [%0], %1;" :: "l"(p), "f"(v));
}

// ---------------- Phase 1: pre = x @ W_xh + b  (fp32 SGEMM, f32x2) --------
// M = B*T = 32768, K = 512, N = 512. Writes straight into d_out (in-place
// pre buffer; the RNN kernel overwrites each element after consuming it).
// Also zeroes g_flag (block 0) so graph replays stay deterministic — the rnn
// kernel launches after this one completes.
#define GTM 128
#define GTN 128
#define GTK 16

__global__ void __launch_bounds__(256, 2)
gemm_pre_kernel(const float* __restrict__ X, const float* __restrict__ W,
                const float* __restrict__ bias, float* __restrict__ out) {
    // reset the sync flags for this launch
    if (blockIdx.x == 0 && blockIdx.y == 0) {
        unsigned* f = &g_flag[0][0][0][0];
        for (int i = threadIdx.x; i < 2 * Bdim * 8 * 8; i += 256) f[i] = 0u;
    }

    __shared__ __align__(16) float As[2][GTK][GTM];  // A stored [k][m] (transposed)
    __shared__ __align__(16) float Bs[2][GTK][GTN];

    const int tid = threadIdx.x;
    const int mb = blockIdx.x * GTM;
    const int nb = blockIdx.y * GTN;
    const int K = Ddim, N = Hdim;

    unsigned long long acc[8][4];
#pragma unroll
    for (int i = 0; i < 8; i++)
#pragma unroll
        for (int q = 0; q < 4; q++) acc[i][q] = 0ull;

    const int tm = (tid >> 4) << 3;  // 8 rows per thread
    const int tn = (tid & 15) << 3;  // 8 cols per thread

    auto loadA = [&](int kt, int buf) {
#pragma unroll
        for (int i = 0; i < 2; i++) {
            int idx = tid + i * 256;          // 0..511 float4 loads
            int row = idx >> 2;               // 0..127
            int kq  = (idx & 3) << 2;         // 0,4,8,12
            float4 v = *(const float4*)(X + (size_t)(mb + row) * K + kt * GTK + kq);
            As[buf][kq + 0][row] = v.x;
            As[buf][kq + 1][row] = v.y;
            As[buf][kq + 2][row] = v.z;
            As[buf][kq + 3][row] = v.w;
        }
    };
    auto loadB = [&](int kt, int buf) {
#pragma unroll
        for (int i = 0; i < 2; i++) {
            int idx = tid + i * 256;
            int kk = idx >> 5;                // 0..15
            int nq = (idx & 31) << 2;         // 0..124
            *(float4*)(&Bs[buf][kk][nq]) =
                *(const float4*)(W + (size_t)(kt * GTK + kk) * N + nb + nq);
        }
    };

    loadA(0, 0);
    loadB(0, 0);
    __syncthreads();

    const int NT = K / GTK;  // 32
    for (int kt = 0; kt < NT; ++kt) {
        const int cur = kt & 1;
        if (kt + 1 < NT) {
            loadA(kt + 1, cur ^ 1);
            loadB(kt + 1, cur ^ 1);
        }
#pragma unroll
        for (int kk = 0; kk < GTK; ++kk) {
            float4 A0 = *(const float4*)(&As[cur][kk][tm]);
            float4 A1 = *(const float4*)(&As[cur][kk][tm + 4]);
            ulonglong2 B0 = *(const ulonglong2*)(&Bs[cur][kk][tn]);
            ulonglong2 B1 = *(const ulonglong2*)(&Bs[cur][kk][tn + 4]);
            float av[8] = {A0.x, A0.y, A0.z, A0.w, A1.x, A1.y, A1.z, A1.w};
#pragma unroll
            for (int mi = 0; mi < 8; ++mi) {
                unsigned long long ai = pk2(av[mi], av[mi]);
                fma2(acc[mi][0], ai, B0.x);
                fma2(acc[mi][1], ai, B0.y);
                fma2(acc[mi][2], ai, B1.x);
                fma2(acc[mi][3], ai, B1.y);
            }
        }
        __syncthreads();
    }

    unsigned long long bz[4];
#pragma unroll
    for (int q = 0; q < 4; q++)
        bz[q] = pk2(bias[nb + tn + 2 * q], bias[nb + tn + 2 * q + 1]);
#pragma unroll
    for (int mi = 0; mi < 8; ++mi) {
#pragma unroll
        for (int q = 0; q < 4; q++) {
            add2(acc[mi][q], bz[q]);
            *(unsigned long long*)(out + (size_t)(mb + tm + mi) * N + nb + tn + 2 * q) =
                acc[mi][q];
        }
    }
}

// ---------------- Phase 2: sequential tanh RNN (L2 flag sync) --------------
// 16 batches x 8 plain CTAs (no clusters). Each CTA owns 64 output columns;
// W_hh[:, slice] register-resident. Per step:
//   writers stcg 64 h-values into g_h[p^1][batch], __syncthreads,
//   tid0 st.release.gpu flag[p^1][batch][rank] = fill-count.
// Each thread's k-chunk (sub) is produced by CTA rank==sub, so it polls only
// flag[p][batch][sub] with ld.acquire.gpu, then ld.global.cg its 256B chunk.
__global__ void __launch_bounds__(512, 1)
rnn_kernel(const float* __restrict__ W_hh, float* __restrict__ out) {
    const int tid  = threadIdx.x;
    const int lane = tid & 31;
    const int warp = tid >> 5;
    const int rank  = blockIdx.x & 7;
    const int batch = blockIdx.x >> 3;

    const int cg   = lane >> 3;        // column-subgroup within warp (0..3)
    const int sub  = lane & 7;         // position within 8-thread reduce group
    const int cloc = warp * 4 + cg;    // local column 0..63
    const int j    = rank * 64 + cloc; // global column 0..511
    const int k0   = sub * 64;         // this thread's k-chunk (produced by CTA 'sub')

    // Load W_hh[k0..k0+63, j] into registers as 32 packed f32x2 pairs.
    unsigned long long w[32];
#pragma unroll
    for (int i = 0; i < 32; i++) {
        float a = W_hh[(size_t)(k0 + 2 * i) * Hdim + j];
        float b = W_hh[(size_t)(k0 + 2 * i + 1) * Hdim + j];
        w[i] = pk2(a, b);
    }

    const bool writer = (sub == 0);  // lanes 0,8,16,24 of each warp
    float* outp = out + (size_t)batch * Tdim * Hdim + j;  // pre in / h out
    float pre_cur = writer ? outp[0] : 0.f;

    const unsigned* myflag[2] = { &g_flag[0][batch][sub][0], &g_flag[1][batch][sub][0] };

    for (int t = 0; t < Tdim; ++t) {
        const int p = t & 1;

        // Prefetch next step's pre (independent of the recurrence).
        float pre_next = 0.f;
        if (writer && (t + 1 < Tdim)) pre_next = outp[(size_t)(t + 1) * Hdim];

        float acc = 0.f;
        if (t > 0) {
            // Wait for my producer CTA's fill of buffer p.
            const unsigned target = (unsigned)(((t - 1) >> 1) + 1);
            while (ldacq(myflag[p]) < target) { }

            // Load my 64-float chunk (L2, bypass stale L1) and accumulate.
            const char* hp = (const char*)&g_h[p][batch][k0];
            unsigned long long acc0 = 0ull, acc1 = 0ull;
#pragma unroll
            for (int i = 0; i < 16; i++) {
                ulonglong2 hv = ldcg128(hp + 16 * i);
                fma2(acc0, hv.x, w[2 * i]);
                fma2(acc1, hv.y, w[2 * i + 1]);
            }
            float2 a0 = upk2(acc0), a1 = upk2(acc1);
            acc = (a0.x + a0.y) + (a1.x + a1.y);
        }

        acc += __shfl_xor_sync(0xffffffffu, acc, 4);
        acc += __shfl_xor_sync(0xffffffffu, acc, 2);
        acc += __shfl_xor_sync(0xffffffffu, acc, 1);

        if (writer) {
            float hn = tanhf(pre_cur + acc);
            outp[(size_t)t * Hdim] = hn;            // final output (batch, t, j)
            if (t + 1 < Tdim) stcg32(&g_h[p ^ 1][batch][j], hn);  // publish state
            pre_cur = pre_next;
        }

        if (t + 1 < Tdim) {
            __syncthreads();  // all 64 writer stores of this CTA issued
            if (tid == 0) {
                strel(&g_flag[p ^ 1][batch][rank][0], (unsigned)((t >> 1) + 1));
            }
        }
    }
}

// ---------------- launch ---------------------------------------------------
extern "C" void kernel_launch(void* const* d_in, const int* in_sizes, int n_in,
                              void* d_out, int out_size) {
    const float* x    = (const float*)d_in[0];  // [16, 2048, 512]
    const float* W_xh = (const float*)d_in[1];  // [512, 512]
    const float* W_hh = (const float*)d_in[2];  // [512, 512]
    const float* b    = (const float*)d_in[3];  // [512]
    // d_in[4] = A (DFA feedback matrix) — backward-only, unused in forward.
    float* out = (float*)d_out;                 // [16, 2048, 512]

    dim3 ggrid((Bdim * Tdim) / GTM, Hdim / GTN);  // (256, 4)
    gemm_pre_kernel<<<ggrid, 256>>>(x, W_xh, b, out);

    // 16 batches x 8 CTAs = 128 plain CTAs (no clusters).
    rnn_kernel<<<128, 512>>>(W_hh, out);
}

// round 4
// speedup vs baseline: 1.6351x; 1.0368x over previous
#include <cuda_runtime.h>
#include <cstdint>
#include <math.h>

#define Bdim 16
#define Tdim 2048
#define Ddim 512
#define Hdim 512

// ---------------- global staging state (no allocations allowed) ------------
__device__ float    g_h[2][Bdim][Hdim];      // double-buffered hidden state
__device__ unsigned g_flag[2][Bdim][8][8];   // [phase][batch][rank][pad 32B]

// ---------------- helpers --------------------------------------------------
__device__ __forceinline__ unsigned long long pk2(float x, float y) {
    unsigned long long r;
    asm("mov.b64 %0, {%1,%2};" : "=l"(r) : "f"(x), "f"(y));
    return r;
}
__device__ __forceinline__ void fma2(unsigned long long& d, unsigned long long a, unsigned long long b) {
    asm("fma.rn.f32x2 %0, %1, %2, %0;" : "+l"(d) : "l"(a), "l"(b));
}
__device__ __forceinline__ void add2(unsigned long long& d, unsigned long long a) {
    asm("add.rn.f32x2 %0, %0, %1;" : "+l"(d) : "l"(a));
}
__device__ __forceinline__ float2 upk2(unsigned long long v) {
    float2 f;
    asm("mov.b64 {%0,%1}, %2;" : "=f"(f.x), "=f"(f.y) : "l"(v));
    return f;
}
__device__ __forceinline__ unsigned ldcg_u32(const unsigned* p) {
    unsigned v;
    asm volatile("ld.global.cg.u32 %0, [%1];" : "=r"(v) : "l"(p) : "memory");
    return v;
}
__device__ __forceinline__ float4 ldcg_f4(const void* p) {
    float4 v;
    asm volatile("ld.global.cg.v4.f32 {%0,%1,%2,%3}, [%4];"
                 : "=f"(v.x), "=f"(v.y), "=f"(v.z), "=f"(v.w) : "l"(p));
    return v;
}
__device__ __forceinline__ void stcg_f4(void* p, float4 v) {
    asm volatile("st.global.cg.v4.f32 [%0], {%1,%2,%3,%4};"
                 :: "l"(p), "f"(v.x), "f"(v.y), "f"(v.z), "f"(v.w) : "memory");
}
__device__ __forceinline__ void red_release_add(unsigned* p, unsigned v) {
    asm volatile("red.release.gpu.global.add.u32 [%0], %1;" :: "l"(p), "r"(v) : "memory");
}

// ---------------- Phase 1: pre = x @ W_xh + b  (fp32 SGEMM, f32x2) --------
// Writes straight into d_out (in-place pre buffer). Block (0,0) also zeroes
// the sync flags so graph replays stay deterministic.
#define GTM 128
#define GTN 128
#define GTK 16

__global__ void __launch_bounds__(256, 2)
gemm_pre_kernel(const float* __restrict__ X, const float* __restrict__ W,
                const float* __restrict__ bias, float* __restrict__ out) {
    if (blockIdx.x == 0 && blockIdx.y == 0) {
        unsigned* f = &g_flag[0][0][0][0];
        for (int i = threadIdx.x; i < 2 * Bdim * 8 * 8; i += 256) f[i] = 0u;
    }

    __shared__ __align__(16) float As[2][GTK][GTM];
    __shared__ __align__(16) float Bs[2][GTK][GTN];

    const int tid = threadIdx.x;
    const int mb = blockIdx.x * GTM;
    const int nb = blockIdx.y * GTN;
    const int K = Ddim, N = Hdim;

    unsigned long long acc[8][4];
#pragma unroll
    for (int i = 0; i < 8; i++)
#pragma unroll
        for (int q = 0; q < 4; q++) acc[i][q] = 0ull;

    const int tm = (tid >> 4) << 3;
    const int tn = (tid & 15) << 3;

    auto loadA = [&](int kt, int buf) {
#pragma unroll
        for (int i = 0; i < 2; i++) {
            int idx = tid + i * 256;
            int row = idx >> 2;
            int kq  = (idx & 3) << 2;
            float4 v = *(const float4*)(X + (size_t)(mb + row) * K + kt * GTK + kq);
            As[buf][kq + 0][row] = v.x;
            As[buf][kq + 1][row] = v.y;
            As[buf][kq + 2][row] = v.z;
            As[buf][kq + 3][row] = v.w;
        }
    };
    auto loadB = [&](int kt, int buf) {
#pragma unroll
        for (int i = 0; i < 2; i++) {
            int idx = tid + i * 256;
            int kk = idx >> 5;
            int nq = (idx & 31) << 2;
            *(float4*)(&Bs[buf][kk][nq]) =
                *(const float4*)(W + (size_t)(kt * GTK + kk) * N + nb + nq);
        }
    };

    loadA(0, 0);
    loadB(0, 0);
    __syncthreads();

    const int NT = K / GTK;
    for (int kt = 0; kt < NT; ++kt) {
        const int cur = kt & 1;
        if (kt + 1 < NT) {
            loadA(kt + 1, cur ^ 1);
            loadB(kt + 1, cur ^ 1);
        }
#pragma unroll
        for (int kk = 0; kk < GTK; ++kk) {
            float4 A0 = *(const float4*)(&As[cur][kk][tm]);
            float4 A1 = *(const float4*)(&As[cur][kk][tm + 4]);
            ulonglong2 B0 = *(const ulonglong2*)(&Bs[cur][kk][tn]);
            ulonglong2 B1 = *(const ulonglong2*)(&Bs[cur][kk][tn + 4]);
            float av[8] = {A0.x, A0.y, A0.z, A0.w, A1.x, A1.y, A1.z, A1.w};
#pragma unroll
            for (int mi = 0; mi < 8; ++mi) {
                unsigned long long ai = pk2(av[mi], av[mi]);
                fma2(acc[mi][0], ai, B0.x);
                fma2(acc[mi][1], ai, B0.y);
                fma2(acc[mi][2], ai, B1.x);
                fma2(acc[mi][3], ai, B1.y);
            }
        }
        __syncthreads();
    }

    unsigned long long bz[4];
#pragma unroll
    for (int q = 0; q < 4; q++)
        bz[q] = pk2(bias[nb + tn + 2 * q], bias[nb + tn + 2 * q + 1]);
#pragma unroll
    for (int mi = 0; mi < 8; ++mi) {
#pragma unroll
        for (int q = 0; q < 4; q++) {
            add2(acc[mi][q], bz[q]);
            *(unsigned long long*)(out + (size_t)(mb + tm + mi) * N + nb + tn + 2 * q) =
                acc[mi][q];
        }
    }
}

// ---------------- Phase 2: sequential tanh RNN (L2 flags, SMEM staging) ----
// 16 batches x 8 plain CTAs. Each CTA owns 64 output columns; W_hh slice in
// registers. Per step:
//   consumer: warp 0 polls the 8 per-producer flags (plain ld.cg, lanes 0-7),
//             stages the 2KB h-vector L2->SMEM, __syncthreads;
//             all warps compute from SMEM (broadcast LDS, conflict-free).
//   producer: per warp, xor-reduce + 3 shfls gather 4 consecutive columns in
//             lane 0 -> st.cg.v4 out, st.cg.v4 g_h, red.release.gpu flag+=1.
//             (release per warp orders data before flag; count hits 16/step)
__global__ void __launch_bounds__(512, 1)
rnn_kernel(const float* __restrict__ W_hh, float* __restrict__ out) {
    __shared__ __align__(16) float sh[2][Hdim];

    const int tid  = threadIdx.x;
    const int lane = tid & 31;
    const int warp = tid >> 5;
    const int rank  = blockIdx.x & 7;
    const int batch = blockIdx.x >> 3;

    const int cg   = lane >> 3;          // column-subgroup within warp (0..3)
    const int sub  = lane & 7;           // position within 8-thread reduce group
    const int j    = rank * 64 + warp * 4 + cg;  // this thread's column
    const int k0   = sub * 64;           // this thread's k-chunk

    // W_hh[k0..k0+63, j] as 32 packed f32x2 pairs.
    unsigned long long w[32];
#pragma unroll
    for (int i = 0; i < 32; i++) {
        float a = W_hh[(size_t)(k0 + 2 * i) * Hdim + j];
        float b = W_hh[(size_t)(k0 + 2 * i + 1) * Hdim + j];
        w[i] = pk2(a, b);
    }

    // zero step-0 buffer
    for (int i = tid; i < Hdim; i += 512) sh[0][i] = 0.f;
    __syncthreads();

    const int jw = rank * 64 + warp * 4;               // lane0's 4-column base
    float* outw = out + (size_t)batch * Tdim * Hdim + jw;
    float4 pre_cur = make_float4(0.f, 0.f, 0.f, 0.f);
    if (lane == 0) pre_cur = ldcg_f4(outw);            // pre for t=0

    for (int t = 0; t < Tdim; ++t) {
        const int p = t & 1;

        if (t > 0 && warp == 0) {
            // ---- poll the 8 producer flags (plain L2 loads, no acquire) ----
            const unsigned tgt = 16u * (unsigned)(((t - 1) >> 1) + 1);
            const unsigned* fp = &g_flag[p][batch][lane & 7][0];
            unsigned ok = (lane < 8) ? 0u : 1u;
            while (true) {
                if (!ok) ok = (ldcg_u32(fp) >= tgt) ? 1u : 0u;
                if (__all_sync(0xffffffffu, ok)) break;
            }
            // ---- stage full 2KB h-vector L2 -> SMEM (4 x 16B per lane) ----
            float4 hv0 = ldcg_f4(&g_h[p][batch][(0 * 32 + lane) * 4]);
            float4 hv1 = ldcg_f4(&g_h[p][batch][(1 * 32 + lane) * 4]);
            float4 hv2 = ldcg_f4(&g_h[p][batch][(2 * 32 + lane) * 4]);
            float4 hv3 = ldcg_f4(&g_h[p][batch][(3 * 32 + lane) * 4]);
            *(float4*)&sh[p][(0 * 32 + lane) * 4] = hv0;
            *(float4*)&sh[p][(1 * 32 + lane) * 4] = hv1;
            *(float4*)&sh[p][(2 * 32 + lane) * 4] = hv2;
            *(float4*)&sh[p][(3 * 32 + lane) * 4] = hv3;
        }
        if (t > 0) __syncthreads();

        // Prefetch next step's pre (independent of recurrence).
        float4 pre_next = make_float4(0.f, 0.f, 0.f, 0.f);
        if (lane == 0 && (t + 1 < Tdim)) pre_next = ldcg_f4(outw + (size_t)(t + 1) * Hdim);

        // ---- partial dot from SMEM: 16 LDS.128 + 32 fma.f32x2 ----
        const ulonglong2* hvp = (const ulonglong2*)(&sh[p][k0]);
        unsigned long long acc0 = 0ull, acc1 = 0ull;
#pragma unroll
        for (int i = 0; i < 16; i++) {
            ulonglong2 hp = hvp[i];
            fma2(acc0, hp.x, w[2 * i]);
            fma2(acc1, hp.y, w[2 * i + 1]);
        }
        float2 a0 = upk2(acc0), a1 = upk2(acc1);
        float acc = (a0.x + a0.y) + (a1.x + a1.y);
        acc += __shfl_xor_sync(0xffffffffu, acc, 4);
        acc += __shfl_xor_sync(0xffffffffu, acc, 2);
        acc += __shfl_xor_sync(0xffffffffu, acc, 1);

        // Gather the warp's 4 column sums into lane 0.
        float s1 = __shfl_sync(0xffffffffu, acc, 8);
        float s2 = __shfl_sync(0xffffffffu, acc, 16);
        float s3 = __shfl_sync(0xffffffffu, acc, 24);

        if (lane == 0) {
            float4 h4;
            h4.x = tanhf(pre_cur.x + acc);
            h4.y = tanhf(pre_cur.y + s1);
            h4.z = tanhf(pre_cur.z + s2);
            h4.w = tanhf(pre_cur.w + s3);
            stcg_f4(outw + (size_t)t * Hdim, h4);        // final output
            if (t + 1 < Tdim) {
                stcg_f4(&g_h[p ^ 1][batch][jw], h4);     // publish state
                red_release_add(&g_flag[p ^ 1][batch][rank][0], 1u);  // data<flag
            }
            pre_cur = pre_next;
        }
    }
}

// ---------------- launch ---------------------------------------------------
extern "C" void kernel_launch(void* const* d_in, const int* in_sizes, int n_in,
                              void* d_out, int out_size) {
    const float* x    = (const float*)d_in[0];  // [16, 2048, 512]
    const float* W_xh = (const float*)d_in[1];  // [512, 512]
    const float* W_hh = (const float*)d_in[2];  // [512, 512]
    const float* b    = (const float*)d_in[3];  // [512]
    // d_in[4] = A (DFA feedback) — backward-only, unused in forward.
    float* out = (float*)d_out;                 // [16, 2048, 512]

    dim3 ggrid((Bdim * Tdim) / GTM, Hdim / GTN);  // (256, 4)
    gemm_pre_kernel<<<ggrid, 256>>>(x, W_xh, b, out);

    rnn_kernel<<<128, 512>>>(W_hh, out);  // 16 batches x 8 CTAs
}

// round 7
// speedup vs baseline: 3.8442x; 2.3511x over previous
#include <cuda_runtime.h>
#include <cstdint>
#include <math.h>

#define Bdim 16
#define Tdim 2048
#define Ddim 512
#define Hdim 512

// ---------------- global staging state (no allocations allowed) ------------
__device__ float    g_h[2][Bdim][Hdim];      // double-buffered hidden state
__device__ unsigned g_flag[2][Bdim][8][8];   // [phase][batch][rank][pad 32B]

// ---------------- helpers --------------------------------------------------
__device__ __forceinline__ unsigned long long pk2(float x, float y) {
    unsigned long long r;
    asm("mov.b64 %0, {%1,%2};" : "=l"(r) : "f"(x), "f"(y));
    return r;
}
__device__ __forceinline__ void fma2(unsigned long long& d, unsigned long long a, unsigned long long b) {
    asm("fma.rn.f32x2 %0, %1, %2, %0;" : "+l"(d) : "l"(a), "l"(b));
}
__device__ __forceinline__ void add2(unsigned long long& d, unsigned long long a) {
    asm("add.rn.f32x2 %0, %0, %1;" : "+l"(d) : "l"(a));
}
__device__ __forceinline__ float2 upk2(unsigned long long v) {
    float2 f;
    asm("mov.b64 {%0,%1}, %2;" : "=f"(f.x), "=f"(f.y) : "l"(v));
    return f;
}
__device__ __forceinline__ unsigned ldcg_u32(const unsigned* p) {
    unsigned v;
    asm volatile("ld.global.cg.u32 %0, [%1];" : "=r"(v) : "l"(p) : "memory");
    return v;
}
__device__ __forceinline__ float4 ldcg_f4(const void* p) {
    float4 v;
    asm volatile("ld.global.cg.v4.f32 {%0,%1,%2,%3}, [%4];"
                 : "=f"(v.x), "=f"(v.y), "=f"(v.z), "=f"(v.w) : "l"(p));
    return v;
}
__device__ __forceinline__ void stcg_f4(void* p, float4 v) {
    asm volatile("st.global.cg.v4.f32 [%0], {%1,%2,%3,%4};"
                 :: "l"(p), "f"(v.x), "f"(v.y), "f"(v.z), "f"(v.w) : "memory");
}
__device__ __forceinline__ void red_release_add(unsigned* p, unsigned v) {
    asm volatile("red.release.gpu.global.add.u32 [%0], %1;" :: "l"(p), "r"(v) : "memory");
}

// ---------------- Phase 1: pre = x @ W_xh + b  (fp32 SGEMM, f32x2) --------
// Writes straight into d_out (in-place pre buffer). Block (0,0) also zeroes
// the sync flags so graph replays stay deterministic.
#define GTM 128
#define GTN 128
#define GTK 16

__global__ void __launch_bounds__(256, 2)
gemm_pre_kernel(const float* __restrict__ X, const float* __restrict__ W,
                const float* __restrict__ bias, float* __restrict__ out) {
    if (blockIdx.x == 0 && blockIdx.y == 0) {
        unsigned* f = &g_flag[0][0][0][0];
        for (int i = threadIdx.x; i < 2 * Bdim * 8 * 8; i += 256) f[i] = 0u;
    }

    __shared__ __align__(16) float As[2][GTK][GTM];
    __shared__ __align__(16) float Bs[2][GTK][GTN];

    const int tid = threadIdx.x;
    const int mb = blockIdx.x * GTM;
    const int nb = blockIdx.y * GTN;
    const int K = Ddim, N = Hdim;

    unsigned long long acc[8][4];
#pragma unroll
    for (int i = 0; i < 8; i++)
#pragma unroll
        for (int q = 0; q < 4; q++) acc[i][q] = 0ull;

    const int tm = (tid >> 4) << 3;
    const int tn = (tid & 15) << 3;

    auto loadA = [&](int kt, int buf) {
#pragma unroll
        for (int i = 0; i < 2; i++) {
            int idx = tid + i * 256;
            int row = idx >> 2;
            int kq  = (idx & 3) << 2;
            float4 v = *(const float4*)(X + (size_t)(mb + row) * K + kt * GTK + kq);
            As[buf][kq + 0][row] = v.x;
            As[buf][kq + 1][row] = v.y;
            As[buf][kq + 2][row] = v.z;
            As[buf][kq + 3][row] = v.w;
        }
    };
    auto loadB = [&](int kt, int buf) {
#pragma unroll
        for (int i = 0; i < 2; i++) {
            int idx = tid + i * 256;
            int kk = idx >> 5;
            int nq = (idx & 31) << 2;
            *(float4*)(&Bs[buf][kk][nq]) =
                *(const float4*)(W + (size_t)(kt * GTK + kk) * N + nb + nq);
        }
    };

    loadA(0, 0);
    loadB(0, 0);
    __syncthreads();

    const int NT = K / GTK;
    for (int kt = 0; kt < NT; ++kt) {
        const int cur = kt & 1;
        if (kt + 1 < NT) {
            loadA(kt + 1, cur ^ 1);
            loadB(kt + 1, cur ^ 1);
        }
#pragma unroll
        for (int kk = 0; kk < GTK; ++kk) {
            float4 A0 = *(const float4*)(&As[cur][kk][tm]);
            float4 A1 = *(const float4*)(&As[cur][kk][tm + 4]);
            ulonglong2 B0 = *(const ulonglong2*)(&Bs[cur][kk][tn]);
            ulonglong2 B1 = *(const ulonglong2*)(&Bs[cur][kk][tn + 4]);
            float av[8] = {A0.x, A0.y, A0.z, A0.w, A1.x, A1.y, A1.z, A1.w};
#pragma unroll
            for (int mi = 0; mi < 8; ++mi) {
                unsigned long long ai = pk2(av[mi], av[mi]);
                fma2(acc[mi][0], ai, B0.x);
                fma2(acc[mi][1], ai, B0.y);
                fma2(acc[mi][2], ai, B1.x);
                fma2(acc[mi][3], ai, B1.y);
            }
        }
        __syncthreads();
    }

    unsigned long long bz[4];
#pragma unroll
    for (int q = 0; q < 4; q++)
        bz[q] = pk2(bias[nb + tn + 2 * q], bias[nb + tn + 2 * q + 1]);
#pragma unroll
    for (int mi = 0; mi < 8; ++mi) {
#pragma unroll
        for (int q = 0; q < 4; q++) {
            add2(acc[mi][q], bz[q]);
            *(unsigned long long*)(out + (size_t)(mb + tm + mi) * N + nb + tn + 2 * q) =
                acc[mi][q];
        }
    }
}

// ---------------- Phase 2: sequential tanh RNN (L2 flags, SMEM staging) ----
// Same sync protocol as round 4 (proven correct). Compute change: k-terms are
// interleaved at 16B granularity — thread 'sub' handles k = 4*sub + 32*i + d
// (i=0..15, d=0..3), so each LDS.128 has lanes sub=0..7 reading 8 consecutive
// 16B chunks = one conflict-free 128B wavefront (was 8-way conflicted before:
// 256B lane stride == 0 mod 128). Cuts LDS crossbar cost ~8x per step.
__global__ void __launch_bounds__(512, 1)
rnn_kernel(const float* __restrict__ W_hh, float* __restrict__ out) {
    __shared__ __align__(16) float sh[2][Hdim];

    const int tid  = threadIdx.x;
    const int lane = tid & 31;
    const int warp = tid >> 5;
    const int rank  = blockIdx.x & 7;
    const int batch = blockIdx.x >> 3;

    const int cg   = lane >> 3;          // column-subgroup within warp (0..3)
    const int sub  = lane & 7;           // position within 8-thread reduce group
    const int j    = rank * 64 + warp * 4 + cg;  // this thread's column
    const int kb   = sub * 4;            // interleaved k-base (16B granule)

    // W_hh[k, j] for k = kb + 32*i + d (d=0..3) as 32 packed f32x2 pairs:
    // w[2i]   = (W[kb+32i+0][j], W[kb+32i+1][j])
    // w[2i+1] = (W[kb+32i+2][j], W[kb+32i+3][j])
    unsigned long long w[32];
#pragma unroll
    for (int i = 0; i < 16; i++) {
        const int k = kb + 32 * i;
        w[2 * i]     = pk2(W_hh[(size_t)(k + 0) * Hdim + j], W_hh[(size_t)(k + 1) * Hdim + j]);
        w[2 * i + 1] = pk2(W_hh[(size_t)(k + 2) * Hdim + j], W_hh[(size_t)(k + 3) * Hdim + j]);
    }

    // zero step-0 buffer
    for (int i = tid; i < Hdim; i += 512) sh[0][i] = 0.f;
    __syncthreads();

    const int jw = rank * 64 + warp * 4;               // lane0's 4-column base
    float* outw = out + (size_t)batch * Tdim * Hdim + jw;
    float4 pre_cur = make_float4(0.f, 0.f, 0.f, 0.f);
    if (lane == 0) pre_cur = ldcg_f4(outw);            // pre for t=0

    for (int t = 0; t < Tdim; ++t) {
        const int p = t & 1;

        if (t > 0 && warp == 0) {
            // ---- poll the 8 producer flags (plain L2 loads, no acquire) ----
            const unsigned tgt = 16u * (unsigned)(((t - 1) >> 1) + 1);
            const unsigned* fp = &g_flag[p][batch][lane & 7][0];
            unsigned ok = (lane < 8) ? 0u : 1u;
            while (true) {
                if (!ok) ok = (ldcg_u32(fp) >= tgt) ? 1u : 0u;
                if (__all_sync(0xffffffffu, ok)) break;
            }
            // ---- stage full 2KB h-vector L2 -> SMEM (4 x 16B per lane) ----
            float4 hv0 = ldcg_f4(&g_h[p][batch][(0 * 32 + lane) * 4]);
            float4 hv1 = ldcg_f4(&g_h[p][batch][(1 * 32 + lane) * 4]);
            float4 hv2 = ldcg_f4(&g_h[p][batch][(2 * 32 + lane) * 4]);
            float4 hv3 = ldcg_f4(&g_h[p][batch][(3 * 32 + lane) * 4]);
            *(float4*)&sh[p][(0 * 32 + lane) * 4] = hv0;
            *(float4*)&sh[p][(1 * 32 + lane) * 4] = hv1;
            *(float4*)&sh[p][(2 * 32 + lane) * 4] = hv2;
            *(float4*)&sh[p][(3 * 32 + lane) * 4] = hv3;
        }
        if (t > 0) __syncthreads();

        // Prefetch next step's pre (independent of recurrence).
        float4 pre_next = make_float4(0.f, 0.f, 0.f, 0.f);
        if (lane == 0 && (t + 1 < Tdim)) pre_next = ldcg_f4(outw + (size_t)(t + 1) * Hdim);

        // ---- partial dot from SMEM: 16 conflict-free LDS.128 + 32 fma2 ----
        // instr i: lane reads sh[kb + 32*i .. +3]  (addr = 16*sub + 128*i)
        unsigned long long acc0 = 0ull, acc1 = 0ull;
#pragma unroll
        for (int i = 0; i < 16; i++) {
            ulonglong2 hp = *(const ulonglong2*)(&sh[p][kb + 32 * i]);
            fma2(acc0, hp.x, w[2 * i]);
            fma2(acc1, hp.y, w[2 * i + 1]);
        }
        float2 a0 = upk2(acc0), a1 = upk2(acc1);
        float acc = (a0.x + a0.y) + (a1.x + a1.y);
        acc += __shfl_xor_sync(0xffffffffu, acc, 4);
        acc += __shfl_xor_sync(0xffffffffu, acc, 2);
        acc += __shfl_xor_sync(0xffffffffu, acc, 1);

        // Gather the warp's 4 column sums into lane 0.
        float s1 = __shfl_sync(0xffffffffu, acc, 8);
        float s2 = __shfl_sync(0xffffffffu, acc, 16);
        float s3 = __shfl_sync(0xffffffffu, acc, 24);

        if (lane == 0) {
            float4 h4;
            h4.x = tanhf(pre_cur.x + acc);
            h4.y = tanhf(pre_cur.y + s1);
            h4.z = tanhf(pre_cur.z + s2);
            h4.w = tanhf(pre_cur.w + s3);
            if (t + 1 < Tdim) {
                stcg_f4(&g_h[p ^ 1][batch][jw], h4);     // publish state first
                red_release_add(&g_flag[p ^ 1][batch][rank][0], 1u);  // data<flag
            }
            stcg_f4(outw + (size_t)t * Hdim, h4);        // final output
            pre_cur = pre_next;
        }
    }
}

// ---------------- launch ---------------------------------------------------
extern "C" void kernel_launch(void* const* d_in, const int* in_sizes, int n_in,
                              void* d_out, int out_size) {
    const float* x    = (const float*)d_in[0];  // [16, 2048, 512]
    const float* W_xh = (const float*)d_in[1];  // [512, 512]
    const float* W_hh = (const float*)d_in[2];  // [512, 512]
    const float* b    = (const float*)d_in[3];  // [512]
    // d_in[4] = A (DFA feedback) — backward-only, unused in forward.
    float* out = (float*)d_out;                 // [16, 2048, 512]

    dim3 ggrid((Bdim * Tdim) / GTM, Hdim / GTN);  // (256, 4)
    gemm_pre_kernel<<<ggrid, 256>>>(x, W_xh, b, out);

    rnn_kernel<<<128, 512>>>(W_hh, out);  // 16 batches x 8 CTAs
}